// round 8
// baseline (speedup 1.0000x reference)
#include <cuda_runtime.h>
#include <cstdint>

// ---------------- problem constants ----------------
#define NBATCH   32
#define C_DIM    256
#define PIX      4096
#define KCL      128
#define OUT_BINS 129
#define TILE_P   128
#define NTH      512                    // 16 warps, warp tile 32px x 32cl
#define KC       32
#define NCHUNK   8
#define A_PITCH  136                    // conflict-free a-frags
#define B_PITCH  36                     // conflict-free b-frags
#define AS_WORDS (KC * A_PITCH)         // 4352
#define BS_WORDS (KCL * B_PITCH)        // 4608
#define STAGE_WORDS (AS_WORDS + BS_WORDS)
#define NSTAGE   3
#define DELTA    1.0f
#define LIST_CAP 2048

__device__ float g_c2[KCL];

// ---------------- helpers ----------------
__device__ __forceinline__ uint32_t smem_u32(const void* p) {
    uint32_t a;
    asm("{ .reg .u64 t; cvta.to.shared.u64 t, %1; cvt.u32.u64 %0, t; }" : "=r"(a) : "l"(p));
    return a;
}
__device__ __forceinline__ uint32_t tf32_rna(float x) {
    uint32_t u;
    asm("cvt.rna.tf32.f32 %0, %1;" : "=r"(u) : "f"(x));
    return u;
}
__device__ __forceinline__ void cpasync16(uint32_t dst, const void* src) {
    asm volatile("cp.async.ca.shared.global [%0], [%1], 16;" :: "r"(dst), "l"(src));
}
__device__ __forceinline__ void mma_tf32(float& d0, float& d1, float& d2, float& d3,
                                         uint32_t a0, uint32_t a1, uint32_t a2, uint32_t a3,
                                         uint32_t b0, uint32_t b1) {
    asm volatile(
        "mma.sync.aligned.m16n8k8.row.col.f32.tf32.tf32.f32 "
        "{%0,%1,%2,%3}, {%4,%5,%6,%7}, {%8,%9}, {%0,%1,%2,%3};"
        : "+f"(d0), "+f"(d1), "+f"(d2), "+f"(d3)
        : "r"(a0), "r"(a1), "r"(a2), "r"(a3), "r"(b0), "r"(b1));
}
__device__ __forceinline__ uint32_t fkey(float f) {
    uint32_t u = __float_as_uint(f);
    return u ^ ((u & 0x80000000u) ? 0xFFFFFFFFu : 0x80000000u);
}
__device__ __forceinline__ float unfkey(uint32_t k) {
    uint32_t u = (k & 0x80000000u) ? (k ^ 0x80000000u) : ~k;
    return __uint_as_float(u);
}

// ---------------- c2 kernel: one warp per cluster ----------------
__global__ void c2_kernel(const float* __restrict__ centers) {
    int warp = (blockIdx.x * blockDim.x + threadIdx.x) >> 5;
    int lane = threadIdx.x & 31;
    if (warp >= KCL) return;
    const float* row = centers + (size_t)warp * C_DIM;
    float s = 0.f;
#pragma unroll
    for (int j = 0; j < 8; ++j) {
        float v = row[lane * 8 + j];
        s = fmaf(v, v, s);
    }
#pragma unroll
    for (int o = 16; o >= 1; o >>= 1) s += __shfl_xor_sync(0xffffffffu, s, o);
    if (lane == 0) g_c2[warp] = s;
}

// ---------------- main kernel ----------------
__global__ __launch_bounds__(NTH, 2)
void vq_mma_kernel(const float* __restrict__ x,
                   const float* __restrict__ centers,
                   float* __restrict__ out) {
    extern __shared__ float smem[];
    const uint32_t smem_b = smem_u32(smem);

    const int tid  = threadIdx.x;
    const int wid  = tid >> 5;              // 0..15
    const int lane = tid & 31;
    const int g    = lane >> 2;             // 0..7
    const int t    = lane & 3;              // 0..3

    const int pm = (wid & 3) * 32;          // pixel quarter
    const int cn = (wid >> 2) * 32;         // cluster quarter

    const int ct = blockIdx.x;
    const int n  = ct >> 5;
    const int p0 = (ct & 31) * TILE_P;
    const float* xn = x + (size_t)n * C_DIM * PIX + p0;

    float acc[2][4][4];
#pragma unroll
    for (int mt = 0; mt < 2; ++mt)
#pragma unroll
        for (int nt = 0; nt < 4; ++nt)
#pragma unroll
            for (int c = 0; c < 4; ++c) acc[mt][nt][c] = 0.f;

    auto issue = [&](int chunk, int s) {
        const int ch0 = chunk * KC;
        const uint32_t sAa = smem_b + (uint32_t)s * STAGE_WORDS * 4u;
        const uint32_t sBa = sAa + AS_WORDS * 4u;
#pragma unroll
        for (int i = 0; i < 2; ++i) {       // x: 1024 segs of 16B
            int idx = tid + NTH * i;
            int ch  = idx >> 5;
            int sg  = idx & 31;
            cpasync16(sAa + (uint32_t)(ch * A_PITCH + sg * 4) * 4u,
                      xn + (size_t)(ch0 + ch) * PIX + sg * 4);
        }
#pragma unroll
        for (int i = 0; i < 2; ++i) {       // centers: 1024 segs
            int idx = tid + NTH * i;
            int cl  = idx >> 3;
            int sg  = idx & 7;
            cpasync16(sBa + (uint32_t)(cl * B_PITCH + sg * 4) * 4u,
                      centers + (size_t)cl * C_DIM + ch0 + sg * 4);
        }
        asm volatile("cp.async.commit_group;" ::: "memory");
    };

    issue(0, 0); issue(1, 1); issue(2, 2);

    for (int c = 0; c < NCHUNK; ++c) {
        if (c <= 5)      asm volatile("cp.async.wait_group 2;" ::: "memory");
        else if (c == 6) asm volatile("cp.async.wait_group 1;" ::: "memory");
        else             asm volatile("cp.async.wait_group 0;" ::: "memory");
        __syncthreads();

        const float* sA = smem + (size_t)(c % NSTAGE) * STAGE_WORDS;
        const float* sB = sA + AS_WORDS;

#pragma unroll
        for (int ks = 0; ks < 4; ++ks) {
            const int kb = ks * 8;
            uint32_t a[2][4];
#pragma unroll
            for (int mt = 0; mt < 2; ++mt) {
                int r = pm + mt * 16 + g;
                a[mt][0] = tf32_rna(sA[(kb + t)     * A_PITCH + r]);
                a[mt][1] = tf32_rna(sA[(kb + t)     * A_PITCH + r + 8]);
                a[mt][2] = tf32_rna(sA[(kb + t + 4) * A_PITCH + r]);
                a[mt][3] = tf32_rna(sA[(kb + t + 4) * A_PITCH + r + 8]);
            }
            uint32_t b[4][2];
#pragma unroll
            for (int nt = 0; nt < 4; ++nt) {
                int cl = cn + nt * 8 + g;
                b[nt][0] = tf32_rna(sB[cl * B_PITCH + kb + t]);
                b[nt][1] = tf32_rna(sB[cl * B_PITCH + kb + t + 4]);
            }
#pragma unroll
            for (int mt = 0; mt < 2; ++mt)
#pragma unroll
                for (int nt = 0; nt < 4; ++nt)
                    mma_tf32(acc[mt][nt][0], acc[mt][nt][1], acc[mt][nt][2], acc[mt][nt][3],
                             a[mt][0], a[mt][1], a[mt][2], a[mt][3],
                             b[nt][0], b[nt][1]);
        }
        __syncthreads();
        if (c + 3 < NCHUNK) issue(c + 3, c % NSTAGE);
    }

    // ---------------- epilogue ----------------
    unsigned long long* tf32key  = reinterpret_cast<unsigned long long*>(smem);       // [128]
    unsigned long long* exactkey = tf32key + 128;                                     // [128]
    unsigned int*       cnt      = reinterpret_cast<unsigned int*>(exactkey + 128);   // [128]
    unsigned int*       list     = cnt + 128;                                         // [LIST_CAP]
    unsigned int*       listn    = list + LIST_CAP;

    __syncthreads();
    if (tid < TILE_P) {
        tf32key[tid]  = ~0ull;
        exactkey[tid] = ~0ull;
        cnt[tid]      = 0u;
    }
    if (tid == 0) *listn = 0u;
    __syncthreads();

    float c2v[4][2];
#pragma unroll
    for (int nt = 0; nt < 4; ++nt) {
        c2v[nt][0] = g_c2[cn + nt * 8 + t * 2];
        c2v[nt][1] = g_c2[cn + nt * 8 + t * 2 + 1];
    }

    // ---- phase A: tf32 argmin per pixel ----
#pragma unroll
    for (int mt = 0; mt < 2; ++mt)
#pragma unroll
        for (int rh = 0; rh < 2; ++rh) {
            const int px = pm + mt * 16 + rh * 8 + g;
            float bv = 3.4e38f; int bk = -1;
#pragma unroll
            for (int nt = 0; nt < 4; ++nt)
#pragma unroll
                for (int cc = 0; cc < 2; ++cc) {
                    float d = fmaf(-2.f, acc[mt][nt][rh * 2 + cc], c2v[nt][cc]);
                    if (d < bv) { bv = d; bk = cn + nt * 8 + t * 2 + cc; }
                }
            unsigned long long key = ((unsigned long long)fkey(bv) << 32) | (unsigned)bk;
            unsigned long long o = __shfl_xor_sync(0xffffffffu, key, 1);
            if (o < key) key = o;
            o = __shfl_xor_sync(0xffffffffu, key, 2);
            if (o < key) key = o;
            if (t == 0) atomicMin(&tf32key[px], key);
        }
    __syncthreads();

    // ---- phase B1: count candidates per pixel ----
#pragma unroll
    for (int mt = 0; mt < 2; ++mt)
#pragma unroll
        for (int rh = 0; rh < 2; ++rh) {
            const int px = pm + mt * 16 + rh * 8 + g;
            const float thr = unfkey((uint32_t)(tf32key[px] >> 32)) + DELTA;
            int cl = 0;
#pragma unroll
            for (int nt = 0; nt < 4; ++nt)
#pragma unroll
                for (int cc = 0; cc < 2; ++cc)
                    if (fmaf(-2.f, acc[mt][nt][rh * 2 + cc], c2v[nt][cc]) <= thr) ++cl;
            if (cl) atomicAdd(&cnt[px], (unsigned)cl);
        }
    __syncthreads();

    // ---- phase B2: push only ambiguous pixels' candidates ----
#pragma unroll
    for (int mt = 0; mt < 2; ++mt)
#pragma unroll
        for (int rh = 0; rh < 2; ++rh) {
            const int px = pm + mt * 16 + rh * 8 + g;
            if (cnt[px] < 2u) continue;
            const float thr = unfkey((uint32_t)(tf32key[px] >> 32)) + DELTA;
#pragma unroll
            for (int nt = 0; nt < 4; ++nt)
#pragma unroll
                for (int cc = 0; cc < 2; ++cc)
                    if (fmaf(-2.f, acc[mt][nt][rh * 2 + cc], c2v[nt][cc]) <= thr) {
                        unsigned e = ((unsigned)px << 8) |
                                     (unsigned)(cn + nt * 8 + t * 2 + cc);
                        unsigned il = atomicAdd(listn, 1u);
                        if (il < LIST_CAP) list[il] = e;
                    }
        }
    __syncthreads();

    // ---- phase C: warp-cooperative exact rescue ----
    const int nl = (int)min(*listn, (unsigned)LIST_CAP);
    for (int i = wid; i < nl; i += 16) {
        unsigned e = list[i];
        int px = e >> 8, k = e & 255;
        const float* cr = centers + (size_t)k * C_DIM;
        float s = 0.f;
#pragma unroll
        for (int j = 0; j < 8; ++j) {
            int cc = lane * 8 + j;
            s = fmaf(__ldg(xn + (size_t)cc * PIX + px), __ldg(cr + cc), s);
        }
#pragma unroll
        for (int o = 16; o >= 1; o >>= 1) s += __shfl_xor_sync(0xffffffffu, s, o);
        if (lane == 0) {
            float ed = fmaf(-2.f, s, g_c2[k]);
            atomicMin(&exactkey[px],
                      ((unsigned long long)fkey(ed) << 32) | (unsigned)k);
        }
    }
    __syncthreads();

    // ---- histogram ----
    if (tid < TILE_P) {
        unsigned long long key = (cnt[tid] >= 2u) ? exactkey[tid] : tf32key[tid];
        int bi = (int)(unsigned)(key & 0xFFFFFFFFull);
        int pg = p0 + tid;
        int h = pg >> 6, w = pg & 63;
        int sblk = (h >> 3) * 8 + (w >> 3);
        atomicAdd(&out[((size_t)n * 64 + sblk) * OUT_BINS + bi + 1], 1.0f / 64.0f);
    }
}

// ---------------- launch ----------------
#define SMEM_BYTES (NSTAGE * STAGE_WORDS * 4)

extern "C" void kernel_launch(void* const* d_in, const int* in_sizes, int n_in,
                              void* d_out, int out_size) {
    const float* x       = (const float*)d_in[0];
    const float* centers = (const float*)d_in[1];
    float* out           = (float*)d_out;

    cudaFuncSetAttribute(vq_mma_kernel, cudaFuncAttributeMaxDynamicSharedMemorySize, SMEM_BYTES);

    cudaMemsetAsync(d_out, 0, (size_t)out_size * sizeof(float), 0);
    c2_kernel<<<(KCL * 32 + 255) / 256, 256>>>(centers);

    int nblocks = (NBATCH * PIX) / TILE_P;   // 1024
    vq_mma_kernel<<<nblocks, NTH, SMEM_BYTES>>>(x, centers, out);
}